// round 9
// baseline (speedup 1.0000x reference)
#include <cuda_runtime.h>
#include <cuda_bf16.h>
#include <math.h>

// Problem sizes (fixed by the reference)
#define B_   32
#define T_   1024
#define D_   1024
#define H_   1024
#define N3_  3072

// Recurrence decomposition: 256 CTAs (2/SM), 4 hidden indices each, 8 warps.
#define NCTA 256
#define JPC  4
#define NWR  8
#define THR  256
#define PPAD 33

// ---------------- packed f32x2 helpers -------------------------------------------
__device__ __forceinline__ void ffma2(unsigned long long &d,
                                      unsigned long long a, unsigned long long b) {
    asm("fma.rn.f32x2 %0, %1, %2, %0;" : "+l"(d) : "l"(a), "l"(b));
}
__device__ __forceinline__ unsigned long long pk2(float a, float b) {
    unsigned long long r;
    asm("mov.b64 %0, {%1, %2};" : "=l"(r) : "f"(a), "f"(b));
    return r;
}
__device__ __forceinline__ void upk2(unsigned long long v, float &a, float &b) {
    asm("mov.b64 {%0, %1}, %2;" : "=f"(a), "=f"(b) : "l"(v));
}
__device__ __forceinline__ void lds_v2_u64(unsigned long long &a, unsigned long long &b,
                                           unsigned addr) {
    asm("ld.shared.v2.b64 {%0, %1}, [%2];" : "=l"(a), "=l"(b) : "r"(addr));
}
__device__ __forceinline__ void ldg_cg_v2_u64(unsigned long long &a, unsigned long long &b,
                                              const void* p) {
    asm("ld.global.cg.v2.b64 {%0, %1}, [%2];" : "=l"(a), "=l"(b) : "l"(p));
}
__device__ __forceinline__ unsigned smem_u32(const void* p) {
    unsigned r;
    asm("{ .reg .u64 t; cvta.to.shared.u64 t, %1; cvt.u32.u64 %0, t; }" : "=r"(r) : "l"(p));
    return r;
}
// release/acquire sync primitives (replace MEMBAR.GPU fences)
__device__ __forceinline__ unsigned ld_acq(volatile unsigned* p) {
    unsigned v;
    asm volatile("ld.acquire.gpu.global.u32 %0, [%1];" : "=r"(v) : "l"((const unsigned*)p));
    return v;
}
__device__ __forceinline__ void st_rel(volatile unsigned* p, unsigned v) {
    asm volatile("st.release.gpu.global.u32 [%0], %1;" :: "l"((unsigned*)p), "r"(v));
}

// ---------------- scratch (static device memory: allocation-guard legal) ---------
__device__ float g_XP[(size_t)B_ * T_ * N3_];   // x_proj [B*T, 3H]
__device__ float g_UT[(size_t)N3_ * H_];        // U transposed: UT[n][k] = U[k][n]
__device__ float g_h[2][H_ * B_];               // h double buffer: [k>>2][b][k&3]
__device__ volatile unsigned g_flags[NCTA];
__device__ volatile unsigned g_epochs[NCTA * 32];   // one 128B line per CTA

// ---------------- reset: graph replays must start from clean state ---------------
__global__ void gru_reset_kernel() {
    int idx = blockIdx.x * blockDim.x + threadIdx.x;
    if (idx < H_ * B_) g_h[0][idx] = 0.0f;
    if (idx < NCTA)      g_flags[idx]  = 0u;
    if (idx < NCTA * 32) g_epochs[idx] = 0u;
}

// ---------------- transpose U[1024][3072] -> UT[3072][1024] ----------------------
__global__ void transpose_u_kernel(const float* __restrict__ U) {
    __shared__ float tile[32][33];
    int bx = blockIdx.x * 32;
    int by = blockIdx.y * 32;
    int x = threadIdx.x;
    int y = threadIdx.y;
#pragma unroll
    for (int i = 0; i < 32; i += 8)
        tile[y + i][x] = U[(size_t)(by + y + i) * N3_ + bx + x];
    __syncthreads();
#pragma unroll
    for (int i = 0; i < 32; i += 8)
        g_UT[(size_t)(bx + y + i) * H_ + by + x] = tile[x][y + i];
}

// ---------------- x_proj SGEMM (FFMA2): C = X @ W + b ----------------------------
__global__ __launch_bounds__(256) void xproj_gemm_kernel(
    const float* __restrict__ X, const float* __restrict__ W,
    const float* __restrict__ bias)
{
    __shared__ float As[16][128];
    __shared__ float Bs[16][128];

    const int tid = threadIdx.x;
    const int m0 = blockIdx.y * 128;
    const int n0 = blockIdx.x * 128;
    const int tx = tid & 15;
    const int ty = tid >> 4;

    const int ar = tid >> 1;
    const int ac = (tid & 1) * 2;
    const int br = tid >> 4;
    const int bc = (tid * 2) & 31;

    unsigned long long acc2[8][4];   // acc2[i][jp] = (C[i][2jp], C[i][2jp+1])
#pragma unroll
    for (int i = 0; i < 8; i++)
#pragma unroll
        for (int j = 0; j < 4; j++) acc2[i][j] = 0ull;

    for (int kt = 0; kt < D_; kt += 16) {
        float4 av0 = *(const float4*)(X + (size_t)(m0 + ar) * D_ + kt + ac * 4);
        float4 av1 = *(const float4*)(X + (size_t)(m0 + ar) * D_ + kt + (ac + 1) * 4);
        As[ac * 4 + 0][ar] = av0.x; As[ac * 4 + 1][ar] = av0.y;
        As[ac * 4 + 2][ar] = av0.z; As[ac * 4 + 3][ar] = av0.w;
        As[ac * 4 + 4][ar] = av1.x; As[ac * 4 + 5][ar] = av1.y;
        As[ac * 4 + 6][ar] = av1.z; As[ac * 4 + 7][ar] = av1.w;
        float4 bv0 = *(const float4*)(W + (size_t)(kt + br) * N3_ + n0 + bc * 4);
        float4 bv1 = *(const float4*)(W + (size_t)(kt + br) * N3_ + n0 + (bc + 1) * 4);
        *(float4*)&Bs[br][bc * 4]       = bv0;
        *(float4*)&Bs[br][(bc + 1) * 4] = bv1;
        __syncthreads();

#pragma unroll
        for (int kk = 0; kk < 16; kk++) {
            float4 a0 = *(const float4*)&As[kk][ty * 8];
            float4 a1 = *(const float4*)&As[kk][ty * 8 + 4];
            float4 b0 = *(const float4*)&Bs[kk][tx * 8];
            float4 b1 = *(const float4*)&Bs[kk][tx * 8 + 4];
            unsigned long long bp[4];
            bp[0] = pk2(b0.x, b0.y); bp[1] = pk2(b0.z, b0.w);
            bp[2] = pk2(b1.x, b1.y); bp[3] = pk2(b1.z, b1.w);
            float av[8] = {a0.x,a0.y,a0.z,a0.w,a1.x,a1.y,a1.z,a1.w};
#pragma unroll
            for (int i = 0; i < 8; i++) {
                unsigned long long ad = pk2(av[i], av[i]);
#pragma unroll
                for (int jp = 0; jp < 4; jp++)
                    ffma2(acc2[i][jp], ad, bp[jp]);
            }
        }
        __syncthreads();
    }

    float bj[8];
#pragma unroll
    for (int j = 0; j < 8; j++) bj[j] = bias[n0 + tx * 8 + j];
#pragma unroll
    for (int i = 0; i < 8; i++) {
        float c[8];
#pragma unroll
        for (int jp = 0; jp < 4; jp++) upk2(acc2[i][jp], c[2*jp], c[2*jp+1]);
        float* outp = g_XP + (size_t)(m0 + ty * 8 + i) * N3_ + n0 + tx * 8;
        float4 v0, v1;
        v0.x = c[0] + bj[0]; v0.y = c[1] + bj[1];
        v0.z = c[2] + bj[2]; v0.w = c[3] + bj[3];
        v1.x = c[4] + bj[4]; v1.y = c[5] + bj[5];
        v1.z = c[6] + bj[6]; v1.w = c[7] + bj[7];
        *(float4*)(outp)     = v0;
        *(float4*)(outp + 4) = v1;
    }
}

// ---------------- activations ----------------------------------------------------
__device__ __forceinline__ float sigm_f(float x) {
    x = fminf(fmaxf(x, -30.0f), 30.0f);
    return 1.0f / (1.0f + expf(-x));
}
__device__ __forceinline__ float tanh_f(float x) {
    float y = fminf(fmaxf(x, -15.0f), 15.0f);
    float e = expf(2.0f * y);
    return (e - 1.0f) / (e + 1.0f);
}

// ---------------- grid barrier: release/acquire chain, per-CTA epoch lines -------
__device__ __forceinline__ void grid_barrier(unsigned target) {
    __syncthreads();                       // CTA's h-writes precede the release below
    if (blockIdx.x == 0) {
        const unsigned tid = threadIdx.x;
        if (tid >= 1 && tid < NCTA)
            while (ld_acq(&g_flags[tid]) < target) { }
        __syncthreads();
        if (tid < NCTA) st_rel(&g_epochs[tid * 32], target);   // fan-out, 1 line/CTA
        __syncthreads();
    } else {
        if (threadIdx.x == 0) {
            st_rel(&g_flags[blockIdx.x], target);
            while (ld_acq(&g_epochs[blockIdx.x * 32]) < target) { }
        }
        __syncthreads();
    }
}

// ---------------- persistent GRU recurrence (FFMA2 GEMM core) --------------------
// 256 CTAs x 256 threads, 2 CTAs/SM. CTA c owns j in [4c, 4c+4) for all 3 gates
// (12 U-columns cached in SMEM). Warp w reduces K-range [128w, 128w+128); lane=b.
__global__ __launch_bounds__(THR, 2) void gru_recur_kernel(
    const float* __restrict__ bias, float* __restrict__ out, int out_size)
{
    extern __shared__ float smem[];
    float* Us   = smem;                 // [12][1024]  (48 KB)
    float* part = smem + 12 * 1024;     // [NWR][12][PPAD]

    const int tid  = threadIdx.x;
    const int warp = tid >> 5;
    const int lane = tid & 31;
    const int j0   = blockIdx.x * JPC;

    // ---- fill SMEM U cache: 12 columns (3 gates x 4 j) ----
    {
        float4* dst = (float4*)Us;
        const int q = H_ / 4;
        for (int i = tid; i < 12 * q; i += THR) {
            const int c  = i / q;
            const int kk = i - c * q;
            const int gate = c >> 2;
            const int jj   = c & 3;
            dst[i] = *(const float4*)(g_UT + (size_t)(gate * H_ + j0 + jj) * H_ + kk * 4);
        }
    }
    __syncthreads();

    const unsigned us_base = smem_u32(Us);

    // combine-phase role (threads 0..127): (j, b) pairs
    const int cjj = tid & 3;
    const int cb  = tid >> 2;
    const int cj  = j0 + cjj;
    const float brz = bias[N3_ + cj];
    const float brr = bias[N3_ + H_ + cj];
    const float brh = bias[N3_ + 2 * H_ + cj];
    const bool  tail = (out_size >= B_ * T_ * H_ + B_ * H_);
    const bool  comb = (tid < JPC * B_);

    const int kq0 = warp * 32;   // this warp's K-range in float4 units (128 k's)

    for (int t = 0; t < T_; t++) {
        const float*  hbuf  = g_h[t & 1];
        float*        hnext = g_h[(t & 1) ^ 1];
        const float4* h4    = (const float4*)hbuf;

        // prefetch combine inputs early (hidden under the GEMM)
        float xz = 0.f, xr = 0.f, xh = 0.f, hold = 0.f;
        if (comb) {
            const float* xp = g_XP + (size_t)(cb * T_ + t) * N3_;
            xz   = __ldcg(xp + cj);
            xr   = __ldcg(xp + H_ + cj);
            xh   = __ldcg(xp + 2 * H_ + cj);
            hold = __ldcg(hbuf + (cj >> 2) * 128 + cb * 4 + (cj & 3));
        }

        // ---- rec = h @ U (this warp's 128-k slice, lane = b, 12 cols) ----
        // acc01[c] accumulates k%4 in {0,1}, acc23[c] accumulates k%4 in {2,3}
        unsigned long long acc01[12], acc23[12];
#pragma unroll
        for (int c = 0; c < 12; c++) { acc01[c] = 0ull; acc23[c] = 0ull; }

        // depth-4 prefetch of h vectors as packed f32x2 pairs
        unsigned long long hp[4][2];
#pragma unroll
        for (int d = 0; d < 4; d++)
            ldg_cg_v2_u64(hp[d][0], hp[d][1], h4 + (size_t)(kq0 + d) * 32 + lane);

#pragma unroll 4
        for (int i = 0; i < 32; i++) {
            unsigned long long h01 = hp[i & 3][0], h23 = hp[i & 3][1];
            if (i + 4 < 32)
                ldg_cg_v2_u64(hp[i & 3][0], hp[i & 3][1],
                              h4 + (size_t)(kq0 + i + 4) * 32 + lane);
            const unsigned uaddr = us_base + (unsigned)((kq0 + i) * 16);
#pragma unroll
            for (int c = 0; c < 12; c++) {
                unsigned long long u01, u23;
                lds_v2_u64(u01, u23, uaddr + (unsigned)(c * (H_ * 4)));
                ffma2(acc01[c], h01, u01);
                ffma2(acc23[c], h23, u23);
            }
        }
#pragma unroll
        for (int c = 0; c < 12; c++) {
            float s0, s1, s2, s3;
            upk2(acc01[c], s0, s1);
            upk2(acc23[c], s2, s3);
            part[(warp * 12 + c) * PPAD + lane] = (s0 + s1) + (s2 + s3);
        }
        __syncthreads();

        // ---- reduce partials + gates + state update (threads 0..127) ----
        if (comb) {
            float rz = brz, rr = brr, rh = brh;
#pragma unroll
            for (int w = 0; w < NWR; w++) {
                rz += part[(w * 12 + cjj) * PPAD + cb];
                rr += part[(w * 12 + 4 + cjj) * PPAD + cb];
                rh += part[(w * 12 + 8 + cjj) * PPAD + cb];
            }
            float z  = sigm_f(xz + rz);
            float r  = sigm_f(xr + rr);
            float hh = tanh_f(xh + r * rh);
            float hn = z * hold + (1.0f - z) * hh;

            out[(size_t)(cb * T_ + t) * H_ + cj] = hn;            // outputs[b][t][j]
            hnext[blockIdx.x * 128 + cb * 4 + cjj] = hn;          // next h (coalesced)
            if (tail && t == T_ - 1)
                out[(size_t)B_ * T_ * H_ + cb * H_ + cj] = hn;    // h_last
        }

        grid_barrier((unsigned)(t + 1));
    }
}

// ---------------- launch ---------------------------------------------------------
extern "C" void kernel_launch(void* const* d_in, const int* in_sizes, int n_in,
                              void* d_out, int out_size) {
    const float* X    = (const float*)d_in[0];   // [B,T,D]
    const float* Wk   = (const float*)d_in[1];   // [D,3H]
    const float* U    = (const float*)d_in[2];   // [H,3H]
    const float* bias = (const float*)d_in[3];   // [2,3H]
    float* out = (float*)d_out;

    const int smem_bytes = (12 * 1024 + NWR * 12 * PPAD) * sizeof(float); // ~61.8 KB
    cudaFuncSetAttribute(gru_recur_kernel,
                         cudaFuncAttributeMaxDynamicSharedMemorySize, smem_bytes);

    gru_reset_kernel<<<256, 256>>>();
    transpose_u_kernel<<<dim3(N3_ / 32, H_ / 32), dim3(32, 8)>>>(U);
    xproj_gemm_kernel<<<dim3(N3_ / 128, (B_ * T_) / 128), 256>>>(X, Wk, bias);
    gru_recur_kernel<<<NCTA, THR, smem_bytes>>>(bias, out, out_size);
}

// round 13
// speedup vs baseline: 1.2173x; 1.2173x over previous
#include <cuda_runtime.h>
#include <cuda_bf16.h>
#include <math.h>
#include <cstdint>

// Problem sizes (fixed by the reference)
#define B_   32
#define T_   1024
#define D_   1024
#define H_   1024
#define N3_  3072

// Recurrence: 128 persistent CTAs = 64 col-tiles (48 cols) x 2 K-splits (512 k)
#define NCTA   128
#define NTHR   256
#define KV_    2
#define CTILE  48
#define KSLICE 512
#define JPC    8
#define KVS    (N3_ * B_)          // g_part kv stride (98304)
#define CPADB  1040                 // padded smem row stride in BYTES (520 bf16)

// SMEM layout (bytes), all 16B aligned
#define SM_UHI  0
#define SM_ULO  (SM_UHI + CTILE * CPADB)        // 49920
#define SM_BHI  (SM_ULO + CTILE * CPADB)        // 99840
#define SM_BLO  (SM_BHI + B_ * CPADB)           // 133120
#define SM_RED  (SM_BLO + B_ * CPADB)           // 166400
#define SM_TOTAL (SM_RED + 8 * CTILE * B_ * 4)  // 166400 + 49152 = 215552

// ---------------- mma.sync m16n8k16 bf16 (baseline sm_80+ PTX, no 'a' target) ---
__device__ __forceinline__ void mma_bf16(float* c, const unsigned* a,
                                         unsigned b0, unsigned b1) {
    asm volatile(
        "mma.sync.aligned.m16n8k16.row.col.f32.bf16.bf16.f32 "
        "{%0,%1,%2,%3}, {%4,%5,%6,%7}, {%8,%9}, {%0,%1,%2,%3};"
        : "+f"(c[0]), "+f"(c[1]), "+f"(c[2]), "+f"(c[3])
        : "r"(a[0]), "r"(a[1]), "r"(a[2]), "r"(a[3]), "r"(b0), "r"(b1));
}
__device__ __forceinline__ unsigned ld_acq(volatile unsigned* p) {
    unsigned v;
    asm volatile("ld.acquire.gpu.global.u32 %0, [%1];" : "=r"(v) : "l"((const unsigned*)p));
    return v;
}
__device__ __forceinline__ void st_rel(volatile unsigned* p, unsigned v) {
    asm volatile("st.release.gpu.global.u32 [%0], %1;" :: "l"((unsigned*)p), "r"(v));
}

// ---------------- scratch (static device memory: allocation-guard legal) ---------
__device__ float g_XP[(size_t)B_ * T_ * N3_];            // x_proj [B*T, 3H]
__device__ float g_UT[(size_t)N3_ * H_];                 // UT[col][k]
__device__ __nv_bfloat16 g_Uhi[(size_t)N3_ * H_];
__device__ __nv_bfloat16 g_Ulo[(size_t)N3_ * H_];
__device__ float g_h1[B_ * H_];                          // h[b][j] fp32
__device__ __nv_bfloat16 g_hhi[B_ * H_];                 // h split hi [b][j]
__device__ __nv_bfloat16 g_hlo[B_ * H_];                 // h split lo [b][j]
__device__ float g_part[KV_ * N3_ * B_];                 // [kv][col][b]
__device__ volatile unsigned g_flags[NCTA];
__device__ volatile unsigned g_epochs[NCTA * 32];        // one 128B line per CTA

// ---------------- reset: graph replays must start from clean state ---------------
__global__ void gru_reset_kernel() {
    int idx = blockIdx.x * blockDim.x + threadIdx.x;
    if (idx < B_ * H_) {
        g_h1[idx]  = 0.0f;
        g_hhi[idx] = __float2bfloat16(0.0f);
        g_hlo[idx] = __float2bfloat16(0.0f);
    }
    if (idx < NCTA)      g_flags[idx]  = 0u;
    if (idx < NCTA * 32) g_epochs[idx] = 0u;
}

// ---------------- transpose U[1024][3072] -> UT[3072][1024] ----------------------
__global__ void transpose_u_kernel(const float* __restrict__ U) {
    __shared__ float tile[32][33];
    int bx = blockIdx.x * 32;   // col dim
    int by = blockIdx.y * 32;   // k dim
    int x = threadIdx.x;
    int y = threadIdx.y;
#pragma unroll
    for (int i = 0; i < 32; i += 8)
        tile[y + i][x] = U[(size_t)(by + y + i) * N3_ + bx + x];
    __syncthreads();
#pragma unroll
    for (int i = 0; i < 32; i += 8)
        g_UT[(size_t)(bx + y + i) * H_ + by + x] = tile[x][y + i];
}

// ---------------- split UT into bf16 hi/lo ---------------------------------------
__global__ void split_u_kernel() {
    size_t i = (size_t)(blockIdx.x * blockDim.x + threadIdx.x) * 4;
    float4 v = *(const float4*)&g_UT[i];
    float f[4] = {v.x, v.y, v.z, v.w};
#pragma unroll
    for (int q = 0; q < 4; q++) {
        __nv_bfloat16 hi = __float2bfloat16_rn(f[q]);
        __nv_bfloat16 lo = __float2bfloat16_rn(f[q] - __bfloat162float(hi));
        g_Uhi[i + q] = hi;
        g_Ulo[i + q] = lo;
    }
}

// ---------------- x_proj SGEMM (plain FFMA, known-good R6 form) ------------------
__global__ __launch_bounds__(256) void xproj_gemm_kernel(
    const float* __restrict__ X, const float* __restrict__ W,
    const float* __restrict__ bias)
{
    __shared__ float As[16][128];
    __shared__ float Bs[16][128];

    const int tid = threadIdx.x;
    const int m0 = blockIdx.y * 128;
    const int n0 = blockIdx.x * 128;
    const int tx = tid & 15;
    const int ty = tid >> 4;

    const int ar = tid >> 1;
    const int ac = (tid & 1) * 2;
    const int br = tid >> 4;
    const int bc = (tid * 2) & 31;

    float acc[8][8];
#pragma unroll
    for (int i = 0; i < 8; i++)
#pragma unroll
        for (int j = 0; j < 8; j++) acc[i][j] = 0.0f;

    for (int kt = 0; kt < D_; kt += 16) {
        float4 av0 = *(const float4*)(X + (size_t)(m0 + ar) * D_ + kt + ac * 4);
        float4 av1 = *(const float4*)(X + (size_t)(m0 + ar) * D_ + kt + (ac + 1) * 4);
        As[ac * 4 + 0][ar] = av0.x; As[ac * 4 + 1][ar] = av0.y;
        As[ac * 4 + 2][ar] = av0.z; As[ac * 4 + 3][ar] = av0.w;
        As[ac * 4 + 4][ar] = av1.x; As[ac * 4 + 5][ar] = av1.y;
        As[ac * 4 + 6][ar] = av1.z; As[ac * 4 + 7][ar] = av1.w;
        float4 bv0 = *(const float4*)(W + (size_t)(kt + br) * N3_ + n0 + bc * 4);
        float4 bv1 = *(const float4*)(W + (size_t)(kt + br) * N3_ + n0 + (bc + 1) * 4);
        *(float4*)&Bs[br][bc * 4]       = bv0;
        *(float4*)&Bs[br][(bc + 1) * 4] = bv1;
        __syncthreads();

#pragma unroll
        for (int kk = 0; kk < 16; kk++) {
            float a[8], b[8];
            float4 a0 = *(const float4*)&As[kk][ty * 8];
            float4 a1 = *(const float4*)&As[kk][ty * 8 + 4];
            float4 b0 = *(const float4*)&Bs[kk][tx * 8];
            float4 b1 = *(const float4*)&Bs[kk][tx * 8 + 4];
            a[0]=a0.x; a[1]=a0.y; a[2]=a0.z; a[3]=a0.w;
            a[4]=a1.x; a[5]=a1.y; a[6]=a1.z; a[7]=a1.w;
            b[0]=b0.x; b[1]=b0.y; b[2]=b0.z; b[3]=b0.w;
            b[4]=b1.x; b[5]=b1.y; b[6]=b1.z; b[7]=b1.w;
#pragma unroll
            for (int i = 0; i < 8; i++)
#pragma unroll
                for (int j = 0; j < 8; j++)
                    acc[i][j] = fmaf(a[i], b[j], acc[i][j]);
        }
        __syncthreads();
    }

    float bj[8];
#pragma unroll
    for (int j = 0; j < 8; j++) bj[j] = bias[n0 + tx * 8 + j];
#pragma unroll
    for (int i = 0; i < 8; i++) {
        float* outp = g_XP + (size_t)(m0 + ty * 8 + i) * N3_ + n0 + tx * 8;
        float4 v0, v1;
        v0.x = acc[i][0] + bj[0]; v0.y = acc[i][1] + bj[1];
        v0.z = acc[i][2] + bj[2]; v0.w = acc[i][3] + bj[3];
        v1.x = acc[i][4] + bj[4]; v1.y = acc[i][5] + bj[5];
        v1.z = acc[i][6] + bj[6]; v1.w = acc[i][7] + bj[7];
        *(float4*)(outp)     = v0;
        *(float4*)(outp + 4) = v1;
    }
}

// ---------------- activations ----------------------------------------------------
__device__ __forceinline__ float sigm_f(float x) {
    x = fminf(fmaxf(x, -30.0f), 30.0f);
    return 1.0f / (1.0f + expf(-x));
}
__device__ __forceinline__ float tanh_f(float x) {
    float y = fminf(fmaxf(x, -15.0f), 15.0f);
    float e = expf(2.0f * y);
    return (e - 1.0f) / (e + 1.0f);
}

// ---------------- grid barrier: per-CTA epoch lines ------------------------------
__device__ __forceinline__ void grid_barrier(unsigned target) {
    __syncthreads();
    if (blockIdx.x == 0) {
        const unsigned tid = threadIdx.x;
        if (tid >= 1 && tid < NCTA)
            while (ld_acq(&g_flags[tid]) < target) { }
        __syncthreads();
        if (tid < NCTA) st_rel(&g_epochs[tid * 32], target);
        __syncthreads();
    } else {
        if (threadIdx.x == 0) {
            st_rel(&g_flags[blockIdx.x], target);
            while (ld_acq(&g_epochs[blockIdx.x * 32]) < target) { }
        }
        __syncthreads();
    }
}

// ---------------- persistent HMMA GRU recurrence ---------------------------------
// CTA = (ctile, kv): D[col0..col0+48)[b 0..32) partial over k in [kv*512,+512),
// bf16x3 via mma.sync m16n8k16. Combine: CTA owns j in [blockIdx*8, +8).
__global__ __launch_bounds__(NTHR, 1) void gru_recur_kernel(
    const float* __restrict__ bias, float* __restrict__ out, int out_size)
{
    extern __shared__ char smem[];
    const int tid  = threadIdx.x;
    const int warp = tid >> 5;
    const int lane = tid & 31;
    const int gid  = lane >> 2;        // mma group id (row within 8)
    const int tq   = lane & 3;         // thread-in-quad (k pair / col pair)
    const int ctile = blockIdx.x >> 1;
    const int kv    = blockIdx.x & 1;
    const int col0  = ctile * CTILE;
    const int k0    = kv * KSLICE;
    const int j0    = blockIdx.x * JPC;

    // ---- preload U hi/lo tile into padded smem (once) ----
    for (int i = tid; i < CTILE * 64; i += NTHR) {     // 64 x 16B per row
        int c = i >> 6, q = i & 63;
        *(uint4*)(smem + SM_UHI + c * CPADB + q * 16) =
            __ldcg((const uint4*)(g_Uhi + (size_t)(col0 + c) * H_ + k0 + q * 8));
        *(uint4*)(smem + SM_ULO + c * CPADB + q * 16) =
            __ldcg((const uint4*)(g_Ulo + (size_t)(col0 + c) * H_ + k0 + q * 8));
    }
    __syncthreads();

    // combine-phase constants: thread = (b = tid>>3, jj = tid&7)
    const int cjj = tid & 7;
    const int cb  = tid >> 3;
    const int cj  = j0 + cjj;
    const float brz = bias[N3_ + cj];
    const float brr = bias[N3_ + H_ + cj];
    const float brh = bias[N3_ + 2 * H_ + cj];
    const bool  tail = (out_size >= B_ * T_ * H_ + B_ * H_);
    const float* pz = g_part + (size_t)(0 * H_ + cj) * B_ + cb;
    const float* pr = g_part + (size_t)(1 * H_ + cj) * B_ + cb;
    const float* ph = g_part + (size_t)(2 * H_ + cj) * B_ + cb;

    const int ktbase = warp * 4;       // this warp's 4 k-tiles (64 k)

    unsigned ep = 0;
    for (int t = 0; t < T_; t++) {
        // prefetch combine inputs (hidden under GEMM)
        const float* xp = g_XP + (size_t)(cb * T_ + t) * N3_;
        float xz   = __ldcg(xp + cj);
        float xr   = __ldcg(xp + H_ + cj);
        float xh   = __ldcg(xp + 2 * H_ + cj);
        float hold = __ldcg(&g_h1[cb * H_ + cj]);

        // ---- copy h k-slice (bf16 hi/lo, written by prev combine) into smem ----
        for (int i = tid; i < B_ * 64; i += NTHR) {    // 32 rows x 64 x 16B
            int b = i >> 6, q = i & 63;
            *(uint4*)(smem + SM_BHI + b * CPADB + q * 16) =
                __ldcg((const uint4*)(g_hhi + b * H_ + k0 + q * 8));
            *(uint4*)(smem + SM_BLO + b * CPADB + q * 16) =
                __ldcg((const uint4*)(g_hlo + b * H_ + k0 + q * 8));
        }
        __syncthreads();

        // ---- HMMA: D[48 x 32] partial; warp covers its 4 k-tiles, all (m,n) ----
        float acc[12][4];
#pragma unroll
        for (int q = 0; q < 12; q++)
#pragma unroll
            for (int r = 0; r < 4; r++) acc[q][r] = 0.0f;

#pragma unroll
        for (int kt = 0; kt < 4; kt++) {
            const int kb = (ktbase + kt) * 32;   // 16 k * 2B
            unsigned ahi[3][4], alo[3][4];
#pragma unroll
            for (int m = 0; m < 3; m++) {
                const char* r0 = smem + (m * 16 + gid) * CPADB + kb + tq * 4;
                const char* r8 = r0 + 8 * CPADB;
                ahi[m][0] = *(const unsigned*)(r0 + SM_UHI);
                ahi[m][1] = *(const unsigned*)(r8 + SM_UHI);
                ahi[m][2] = *(const unsigned*)(r0 + SM_UHI + 16);
                ahi[m][3] = *(const unsigned*)(r8 + SM_UHI + 16);
                alo[m][0] = *(const unsigned*)(r0 + SM_ULO);
                alo[m][1] = *(const unsigned*)(r8 + SM_ULO);
                alo[m][2] = *(const unsigned*)(r0 + SM_ULO + 16);
                alo[m][3] = *(const unsigned*)(r8 + SM_ULO + 16);
            }
#pragma unroll
            for (int n = 0; n < 4; n++) {
                const char* brow = smem + (n * 8 + gid) * CPADB + kb + tq * 4;
                unsigned bh0 = *(const unsigned*)(brow + SM_BHI);
                unsigned bh1 = *(const unsigned*)(brow + SM_BHI + 16);
                unsigned bl0 = *(const unsigned*)(brow + SM_BLO);
                unsigned bl1 = *(const unsigned*)(brow + SM_BLO + 16);
#pragma unroll
                for (int m = 0; m < 3; m++) {
                    mma_bf16(acc[m * 4 + n], ahi[m], bh0, bh1);
                    mma_bf16(acc[m * 4 + n], ahi[m], bl0, bl1);
                    mma_bf16(acc[m * 4 + n], alo[m], bh0, bh1);
                }
            }
        }

        // ---- write warp partials to smem red[warp][col48][b32] ----
        {
            float* red = (float*)(smem + SM_RED) + warp * (CTILE * B_);
#pragma unroll
            for (int m = 0; m < 3; m++)
#pragma unroll
                for (int n = 0; n < 4; n++) {
                    int col = m * 16 + gid;
                    int b   = n * 8 + tq * 2;
                    *(float2*)&red[col * B_ + b] =
                        make_float2(acc[m * 4 + n][0], acc[m * 4 + n][1]);
                    *(float2*)&red[(col + 8) * B_ + b] =
                        make_float2(acc[m * 4 + n][2], acc[m * 4 + n][3]);
                }
        }
        __syncthreads();

        // ---- reduce 8 warps, store to g_part[kv][col][b] ----
        {
            const float* redb = (const float*)(smem + SM_RED);
            for (int i = tid; i < (CTILE * B_) / 2; i += NTHR) {   // 768 float2
                float2 s = make_float2(0.f, 0.f);
#pragma unroll
                for (int w = 0; w < 8; w++) {
                    float2 v = *(const float2*)&redb[w * (CTILE * B_) + i * 2];
                    s.x += v.x; s.y += v.y;
                }
                int col = (i * 2) >> 5, b = (i * 2) & 31;
                *(float2*)(g_part + (size_t)kv * KVS + (size_t)(col0 + col) * B_ + b) = s;
            }
        }

        grid_barrier(++ep);   // partials visible

        // ---- combine: reduce 2 kv partials, gates, state update ----
        {
            float rz = brz, rr = brr, rh = brh;
#pragma unroll
            for (int v = 0; v < KV_; v++) {
                rz += __ldcg(pz + (size_t)v * KVS);
                rr += __ldcg(pr + (size_t)v * KVS);
                rh += __ldcg(ph + (size_t)v * KVS);
            }
            float z  = sigm_f(xz + rz);
            float r  = sigm_f(xr + rr);
            float hh = tanh_f(xh + r * rh);
            float hn = z * hold + (1.0f - z) * hh;

            out[(size_t)(cb * T_ + t) * H_ + cj] = hn;
            g_h1[cb * H_ + cj] = hn;
            __nv_bfloat16 hi = __float2bfloat16_rn(hn);
            __nv_bfloat16 lo = __float2bfloat16_rn(hn - __bfloat162float(hi));
            g_hhi[cb * H_ + cj] = hi;
            g_hlo[cb * H_ + cj] = lo;
            if (tail && t == T_ - 1)
                out[(size_t)B_ * T_ * H_ + cb * H_ + cj] = hn;
        }

        grid_barrier(++ep);   // h (fp32 + splits) ready for next step
    }
}

// ---------------- launch ---------------------------------------------------------
extern "C" void kernel_launch(void* const* d_in, const int* in_sizes, int n_in,
                              void* d_out, int out_size) {
    const float* X    = (const float*)d_in[0];   // [B,T,D]
    const float* Wk   = (const float*)d_in[1];   // [D,3H]
    const float* U    = (const float*)d_in[2];   // [H,3H]
    const float* bias = (const float*)d_in[3];   // [2,3H]
    float* out = (float*)d_out;

    cudaFuncSetAttribute(gru_recur_kernel,
                         cudaFuncAttributeMaxDynamicSharedMemorySize, SM_TOTAL);

    gru_reset_kernel<<<256, 256>>>();
    transpose_u_kernel<<<dim3(N3_ / 32, H_ / 32), dim3(32, 8)>>>(U);
    split_u_kernel<<<(N3_ * H_) / (256 * 4), 256>>>();
    xproj_gemm_kernel<<<dim3(N3_ / 128, (B_ * T_) / 128), 256>>>(X, Wk, bias);
    gru_recur_kernel<<<NCTA, NTHR, SM_TOTAL>>>(bias, out, out_size);
}

// round 14
// speedup vs baseline: 1.3158x; 1.0810x over previous
#include <cuda_runtime.h>
#include <cuda_bf16.h>
#include <math.h>
#include <cstdint>

// Problem sizes (fixed by the reference)
#define B_   32
#define T_   1024
#define D_   1024
#define H_   1024
#define N3_  3072

// Recurrence: 128 persistent CTAs; CTA owns 8 j's (24 gate-columns), full K=1024.
#define NCTA   128
#define NTHR   256
#define JPC    8
#define UPADB  2064                 // padded U smem row stride bytes (1024*2 + 16)
#define REDW   832                  // per-warp red stride in floats (32 * 26)

// SMEM layout (bytes)
#define SM_UHI  0
#define SM_ULO  (SM_UHI + 24 * UPADB)     // 49536
#define SM_RED  (SM_ULO + 24 * UPADB)     // 99072
#define SM_TOTAL (SM_RED + 8 * REDW * 4)  // 99072 + 26624 = 125696

// ---------------- mma.sync m16n8k16 bf16 (baseline sm_80+ PTX) -------------------
__device__ __forceinline__ void mma_bf16(float* c, const unsigned* a,
                                         unsigned b0, unsigned b1) {
    asm volatile(
        "mma.sync.aligned.m16n8k16.row.col.f32.bf16.bf16.f32 "
        "{%0,%1,%2,%3}, {%4,%5,%6,%7}, {%8,%9}, {%0,%1,%2,%3};"
        : "+f"(c[0]), "+f"(c[1]), "+f"(c[2]), "+f"(c[3])
        : "r"(a[0]), "r"(a[1]), "r"(a[2]), "r"(a[3]), "r"(b0), "r"(b1));
}
__device__ __forceinline__ unsigned ld_acq(volatile unsigned* p) {
    unsigned v;
    asm volatile("ld.acquire.gpu.global.u32 %0, [%1];" : "=r"(v) : "l"((const unsigned*)p));
    return v;
}
__device__ __forceinline__ void st_rel(volatile unsigned* p, unsigned v) {
    asm volatile("st.release.gpu.global.u32 [%0], %1;" :: "l"((unsigned*)p), "r"(v));
}

// ---------------- scratch (static device memory: allocation-guard legal) ---------
__device__ float g_XP[(size_t)B_ * T_ * N3_];            // x_proj [B*T, 3H]
__device__ float g_UT[(size_t)N3_ * H_];                 // UT[col][k]
__device__ __nv_bfloat16 g_Uhi[(size_t)N3_ * H_];
__device__ __nv_bfloat16 g_Ulo[(size_t)N3_ * H_];
__device__ __nv_bfloat16 g_hhi[2][B_ * H_];              // h split hi, double-buffered
__device__ __nv_bfloat16 g_hlo[2][B_ * H_];              // h split lo, double-buffered
__device__ volatile unsigned g_flags[NCTA];
__device__ volatile unsigned g_epochs[NCTA * 32];        // one 128B line per CTA

// ---------------- reset: graph replays must start from clean state ---------------
__global__ void gru_reset_kernel() {
    int idx = blockIdx.x * blockDim.x + threadIdx.x;
    if (idx < B_ * H_) {
        __nv_bfloat16 z = __float2bfloat16(0.0f);
        g_hhi[0][idx] = z; g_hlo[0][idx] = z;
        g_hhi[1][idx] = z; g_hlo[1][idx] = z;
    }
    if (idx < NCTA)      g_flags[idx]  = 0u;
    if (idx < NCTA * 32) g_epochs[idx] = 0u;
}

// ---------------- transpose U[1024][3072] -> UT[3072][1024] ----------------------
__global__ void transpose_u_kernel(const float* __restrict__ U) {
    __shared__ float tile[32][33];
    int bx = blockIdx.x * 32;   // col dim
    int by = blockIdx.y * 32;   // k dim
    int x = threadIdx.x;
    int y = threadIdx.y;
#pragma unroll
    for (int i = 0; i < 32; i += 8)
        tile[y + i][x] = U[(size_t)(by + y + i) * N3_ + bx + x];
    __syncthreads();
#pragma unroll
    for (int i = 0; i < 32; i += 8)
        g_UT[(size_t)(bx + y + i) * H_ + by + x] = tile[x][y + i];
}

// ---------------- split UT into bf16 hi/lo ---------------------------------------
__global__ void split_u_kernel() {
    size_t i = (size_t)(blockIdx.x * blockDim.x + threadIdx.x) * 4;
    float4 v = *(const float4*)&g_UT[i];
    float f[4] = {v.x, v.y, v.z, v.w};
#pragma unroll
    for (int q = 0; q < 4; q++) {
        __nv_bfloat16 hi = __float2bfloat16_rn(f[q]);
        __nv_bfloat16 lo = __float2bfloat16_rn(f[q] - __bfloat162float(hi));
        g_Uhi[i + q] = hi;
        g_Ulo[i + q] = lo;
    }
}

// ---------------- x_proj SGEMM (plain FFMA, known-good R6 form) ------------------
__global__ __launch_bounds__(256) void xproj_gemm_kernel(
    const float* __restrict__ X, const float* __restrict__ W,
    const float* __restrict__ bias)
{
    __shared__ float As[16][128];
    __shared__ float Bs[16][128];

    const int tid = threadIdx.x;
    const int m0 = blockIdx.y * 128;
    const int n0 = blockIdx.x * 128;
    const int tx = tid & 15;
    const int ty = tid >> 4;

    const int ar = tid >> 1;
    const int ac = (tid & 1) * 2;
    const int br = tid >> 4;
    const int bc = (tid * 2) & 31;

    float acc[8][8];
#pragma unroll
    for (int i = 0; i < 8; i++)
#pragma unroll
        for (int j = 0; j < 8; j++) acc[i][j] = 0.0f;

    for (int kt = 0; kt < D_; kt += 16) {
        float4 av0 = *(const float4*)(X + (size_t)(m0 + ar) * D_ + kt + ac * 4);
        float4 av1 = *(const float4*)(X + (size_t)(m0 + ar) * D_ + kt + (ac + 1) * 4);
        As[ac * 4 + 0][ar] = av0.x; As[ac * 4 + 1][ar] = av0.y;
        As[ac * 4 + 2][ar] = av0.z; As[ac * 4 + 3][ar] = av0.w;
        As[ac * 4 + 4][ar] = av1.x; As[ac * 4 + 5][ar] = av1.y;
        As[ac * 4 + 6][ar] = av1.z; As[ac * 4 + 7][ar] = av1.w;
        float4 bv0 = *(const float4*)(W + (size_t)(kt + br) * N3_ + n0 + bc * 4);
        float4 bv1 = *(const float4*)(W + (size_t)(kt + br) * N3_ + n0 + (bc + 1) * 4);
        *(float4*)&Bs[br][bc * 4]       = bv0;
        *(float4*)&Bs[br][(bc + 1) * 4] = bv1;
        __syncthreads();

#pragma unroll
        for (int kk = 0; kk < 16; kk++) {
            float a[8], b[8];
            float4 a0 = *(const float4*)&As[kk][ty * 8];
            float4 a1 = *(const float4*)&As[kk][ty * 8 + 4];
            float4 b0 = *(const float4*)&Bs[kk][tx * 8];
            float4 b1 = *(const float4*)&Bs[kk][tx * 8 + 4];
            a[0]=a0.x; a[1]=a0.y; a[2]=a0.z; a[3]=a0.w;
            a[4]=a1.x; a[5]=a1.y; a[6]=a1.z; a[7]=a1.w;
            b[0]=b0.x; b[1]=b0.y; b[2]=b0.z; b[3]=b0.w;
            b[4]=b1.x; b[5]=b1.y; b[6]=b1.z; b[7]=b1.w;
#pragma unroll
            for (int i = 0; i < 8; i++)
#pragma unroll
                for (int j = 0; j < 8; j++)
                    acc[i][j] = fmaf(a[i], b[j], acc[i][j]);
        }
        __syncthreads();
    }

    float bj[8];
#pragma unroll
    for (int j = 0; j < 8; j++) bj[j] = bias[n0 + tx * 8 + j];
#pragma unroll
    for (int i = 0; i < 8; i++) {
        float* outp = g_XP + (size_t)(m0 + ty * 8 + i) * N3_ + n0 + tx * 8;
        float4 v0, v1;
        v0.x = acc[i][0] + bj[0]; v0.y = acc[i][1] + bj[1];
        v0.z = acc[i][2] + bj[2]; v0.w = acc[i][3] + bj[3];
        v1.x = acc[i][4] + bj[4]; v1.y = acc[i][5] + bj[5];
        v1.z = acc[i][6] + bj[6]; v1.w = acc[i][7] + bj[7];
        *(float4*)(outp)     = v0;
        *(float4*)(outp + 4) = v1;
    }
}

// ---------------- activations ----------------------------------------------------
__device__ __forceinline__ float sigm_f(float x) {
    x = fminf(fmaxf(x, -30.0f), 30.0f);
    return 1.0f / (1.0f + expf(-x));
}
__device__ __forceinline__ float tanh_f(float x) {
    float y = fminf(fmaxf(x, -15.0f), 15.0f);
    float e = expf(2.0f * y);
    return (e - 1.0f) / (e + 1.0f);
}

// ---------------- grid barrier: per-CTA epoch lines ------------------------------
__device__ __forceinline__ void grid_barrier(unsigned target) {
    __syncthreads();
    if (blockIdx.x == 0) {
        const unsigned tid = threadIdx.x;
        if (tid >= 1 && tid < NCTA)
            while (ld_acq(&g_flags[tid]) < target) { }
        __syncthreads();
        if (tid < NCTA) st_rel(&g_epochs[tid * 32], target);
        __syncthreads();
    } else {
        if (threadIdx.x == 0) {
            st_rel(&g_flags[blockIdx.x], target);
            while (ld_acq(&g_epochs[blockIdx.x * 32]) < target) { }
        }
        __syncthreads();
    }
}

// ---------------- persistent HMMA GRU recurrence (1 barrier/step) ----------------
// CTA bid owns j in [8*bid, 8*bid+8): its 24 U-columns {z,r,h}x8j, FULL K=1024.
// Warp w reduces k in [128w, 128w+128). A = h (m32, from global), B = U (n24, smem).
// Local 8-warp smem reduce -> CTA-local combine -> double-buffered h splits.
__global__ __launch_bounds__(NTHR, 1) void gru_recur_kernel(
    const float* __restrict__ bias, float* __restrict__ out, int out_size)
{
    extern __shared__ char smem[];
    float* redf = (float*)(smem + SM_RED);
    const int tid  = threadIdx.x;
    const int warp = tid >> 5;
    const int lane = tid & 31;
    const int gid  = lane >> 2;        // mma group id
    const int tq   = lane & 3;         // thread-in-quad
    const int j0   = blockIdx.x * JPC;

    // ---- preload this CTA's 24 U columns (gate-major: col = gate*8 + jj) --------
    for (int i = tid; i < 24 * 128; i += NTHR) {       // 128 x 16B per column
        int c = i >> 7, q = i & 127;
        int grow = (c >> 3) * H_ + j0 + (c & 7);       // global U column
        *(uint4*)(smem + SM_UHI + c * UPADB + q * 16) =
            __ldcg((const uint4*)(g_Uhi + (size_t)grow * H_ + q * 8));
        *(uint4*)(smem + SM_ULO + c * UPADB + q * 16) =
            __ldcg((const uint4*)(g_Ulo + (size_t)grow * H_ + q * 8));
    }
    __syncthreads();

    // combine role: thread = (b = tid>>3, jj = tid&7); 256 threads = 32x8 exactly
    const int cjj = tid & 7;
    const int cb  = tid >> 3;
    const int cj  = j0 + cjj;
    const float brz = bias[N3_ + cj];
    const float brr = bias[N3_ + H_ + cj];
    const float brh = bias[N3_ + 2 * H_ + cj];
    const bool  tail = (out_size >= B_ * T_ * H_ + B_ * H_);
    float hold = 0.0f;                 // h[b][j] stays in-register across steps

    const int kw0 = warp * 128;        // this warp's K-range

    for (int t = 0; t < T_; t++) {
        const __nv_bfloat16* Hhi = g_hhi[t & 1];
        const __nv_bfloat16* Hlo = g_hlo[t & 1];
        __nv_bfloat16* Whi = g_hhi[(t & 1) ^ 1];
        __nv_bfloat16* Wlo = g_hlo[(t & 1) ^ 1];

        // prefetch combine inputs (hidden under GEMM)
        const float* xp = g_XP + (size_t)(cb * T_ + t) * N3_;
        float xz = __ldcg(xp + cj);
        float xr = __ldcg(xp + H_ + cj);
        float xh = __ldcg(xp + 2 * H_ + cj);

        // ---- HMMA: D[32 b][24 col] partial over this warp's 128 k ----
        float acc[2][3][4];
#pragma unroll
        for (int m = 0; m < 2; m++)
#pragma unroll
            for (int n = 0; n < 3; n++)
#pragma unroll
                for (int r = 0; r < 4; r++) acc[m][n][r] = 0.0f;

#pragma unroll
        for (int kt = 0; kt < 8; kt++) {
            const int kg = kw0 + kt * 16;
            // A = h fragments (hi/lo) straight from global (L2), rows = b
            unsigned ahi[2][4], alo[2][4];
#pragma unroll
            for (int m = 0; m < 2; m++) {
                const __nv_bfloat16* ph = Hhi + (size_t)(m * 16 + gid) * H_ + kg + 2 * tq;
                const __nv_bfloat16* pl = Hlo + (size_t)(m * 16 + gid) * H_ + kg + 2 * tq;
                ahi[m][0] = __ldcg((const unsigned*)ph);
                ahi[m][1] = __ldcg((const unsigned*)(ph + 8 * H_));
                ahi[m][2] = __ldcg((const unsigned*)(ph + 8));
                ahi[m][3] = __ldcg((const unsigned*)(ph + 8 * H_ + 8));
                alo[m][0] = __ldcg((const unsigned*)pl);
                alo[m][1] = __ldcg((const unsigned*)(pl + 8 * H_));
                alo[m][2] = __ldcg((const unsigned*)(pl + 8));
                alo[m][3] = __ldcg((const unsigned*)(pl + 8 * H_ + 8));
            }
#pragma unroll
            for (int n = 0; n < 3; n++) {
                // B = U column (n*8 + gid), k = kg + 2tq (+8)
                const char* ub = smem + (n * 8 + gid) * UPADB + (kg + 2 * tq) * 2;
                unsigned bh0 = *(const unsigned*)(ub + SM_UHI);
                unsigned bh1 = *(const unsigned*)(ub + SM_UHI + 16);
                unsigned bl0 = *(const unsigned*)(ub + SM_ULO);
                unsigned bl1 = *(const unsigned*)(ub + SM_ULO + 16);
#pragma unroll
                for (int m = 0; m < 2; m++) {
                    mma_bf16(acc[m][n], ahi[m], bh0, bh1);
                    mma_bf16(acc[m][n], ahi[m], bl0, bl1);
                    mma_bf16(acc[m][n], alo[m], bh0, bh1);
                }
            }
        }

        // ---- write warp partials: red[warp][b(32)][col(24, pad 26)] ----
        {
            float* red = redf + warp * REDW;
#pragma unroll
            for (int m = 0; m < 2; m++)
#pragma unroll
                for (int n = 0; n < 3; n++) {
                    int b   = m * 16 + gid;
                    int col = n * 8 + 2 * tq;
                    *(float2*)&red[b * 26 + col] =
                        make_float2(acc[m][n][0], acc[m][n][1]);
                    *(float2*)&red[(b + 8) * 26 + col] =
                        make_float2(acc[m][n][2], acc[m][n][3]);
                }
        }
        __syncthreads();

        // ---- CTA-local: reduce 8 warps + gates + state update ----
        {
            float rz = brz, rr = brr, rh = brh;
#pragma unroll
            for (int w = 0; w < 8; w++) {
                const float* r = redf + w * REDW + cb * 26;
                rz += r[cjj];
                rr += r[8 + cjj];
                rh += r[16 + cjj];
            }
            float z  = sigm_f(xz + rz);
            float r  = sigm_f(xr + rr);
            float hh = tanh_f(xh + r * rh);
            float hn = z * hold + (1.0f - z) * hh;
            hold = hn;

            out[(size_t)(cb * T_ + t) * H_ + cj] = hn;
            __nv_bfloat16 hi = __float2bfloat16_rn(hn);
            __nv_bfloat16 lo = __float2bfloat16_rn(hn - __bfloat162float(hi));
            Whi[cb * H_ + cj] = hi;
            Wlo[cb * H_ + cj] = lo;
            if (tail && t == T_ - 1)
                out[(size_t)B_ * T_ * H_ + cb * H_ + cj] = hn;
        }

        grid_barrier((unsigned)(t + 1));   // h[t+1] splits visible to all
    }
}

// ---------------- launch ---------------------------------------------------------
extern "C" void kernel_launch(void* const* d_in, const int* in_sizes, int n_in,
                              void* d_out, int out_size) {
    const float* X    = (const float*)d_in[0];   // [B,T,D]
    const float* Wk   = (const float*)d_in[1];   // [D,3H]
    const float* U    = (const float*)d_in[2];   // [H,3H]
    const float* bias = (const float*)d_in[3];   // [2,3H]
    float* out = (float*)d_out;

    cudaFuncSetAttribute(gru_recur_kernel,
                         cudaFuncAttributeMaxDynamicSharedMemorySize, SM_TOTAL);

    gru_reset_kernel<<<256, 256>>>();
    transpose_u_kernel<<<dim3(N3_ / 32, H_ / 32), dim3(32, 8)>>>(U);
    split_u_kernel<<<(N3_ * H_) / (256 * 4), 256>>>();
    xproj_gemm_kernel<<<dim3(N3_ / 128, (B_ * T_) / 128), 256>>>(X, Wk, bias);
    gru_recur_kernel<<<NCTA, NTHR, SM_TOTAL>>>(bias, out, out_size);
}